// round 3
// baseline (speedup 1.0000x reference)
#include <cuda_runtime.h>
#include <cstdint>

// Problem constants (fixed by the dataset: N=2048, DIM=16, E=65536)
#define NN 2048
#define DD 16
#define BITMAP_WORDS ((NN * NN) / 32)   // 131072 words = 512 KB

// scratch (no cudaMalloc allowed)
__device__ float    g_a[NN];                 // dot(e[i], W[0:16])
__device__ float    g_c[NN];                 // dot(e[i], W[16:32])
__device__ unsigned g_bitmap[BITMAP_WORDS];  // adjacency bitmap (L2-resident)

// ---------------------------------------------------------------------------
// Kernel 1: per-node dots + zero the bitmap.
// Grid 128x256 = 32768 threads. First 2048 threads do the dots; every thread
// zeroes one uint4 (16B) of the bitmap -> 512KB, single pass, no loop.
// ---------------------------------------------------------------------------
__global__ void __launch_bounds__(256)
precompute_and_zero(const float* __restrict__ e,
                    const float* __restrict__ W, int n) {
    int t = blockIdx.x * blockDim.x + threadIdx.x;
    if (t < n) {
        const float4* e4 = (const float4*)(e + t * DD);
        float4 r0 = __ldg(&e4[0]), r1 = __ldg(&e4[1]);
        float4 r2 = __ldg(&e4[2]), r3 = __ldg(&e4[3]);
        float a = r0.x * __ldg(&W[0])  + r0.y * __ldg(&W[1])
                + r0.z * __ldg(&W[2])  + r0.w * __ldg(&W[3])
                + r1.x * __ldg(&W[4])  + r1.y * __ldg(&W[5])
                + r1.z * __ldg(&W[6])  + r1.w * __ldg(&W[7])
                + r2.x * __ldg(&W[8])  + r2.y * __ldg(&W[9])
                + r2.z * __ldg(&W[10]) + r2.w * __ldg(&W[11])
                + r3.x * __ldg(&W[12]) + r3.y * __ldg(&W[13])
                + r3.z * __ldg(&W[14]) + r3.w * __ldg(&W[15]);
        float c = r0.x * __ldg(&W[16]) + r0.y * __ldg(&W[17])
                + r0.z * __ldg(&W[18]) + r0.w * __ldg(&W[19])
                + r1.x * __ldg(&W[20]) + r1.y * __ldg(&W[21])
                + r1.z * __ldg(&W[22]) + r1.w * __ldg(&W[23])
                + r2.x * __ldg(&W[24]) + r2.y * __ldg(&W[25])
                + r2.z * __ldg(&W[26]) + r2.w * __ldg(&W[27])
                + r3.x * __ldg(&W[28]) + r3.y * __ldg(&W[29])
                + r3.z * __ldg(&W[30]) + r3.w * __ldg(&W[31]);
        g_a[t] = a;
        g_c[t] = c;
    }
    ((uint4*)g_bitmap)[t] = make_uint4(0u, 0u, 0u, 0u);
}

// ---------------------------------------------------------------------------
// Kernel 2: scatter true-edge bits. edge_list: [2, E] row-major.
// ---------------------------------------------------------------------------
__global__ void scatter_bits(const int* __restrict__ el, int E, int n) {
    int t = blockIdx.x * blockDim.x + threadIdx.x;
    if (t >= E) return;
    unsigned p = (unsigned)el[t] * (unsigned)n + (unsigned)el[E + t];
    atomicOr(&g_bitmap[p >> 5], 1u << (p & 31u));
}

// ---------------------------------------------------------------------------
// Kernel 3 (the big one): one block per row i. Thread = (k = tid&7 lane role,
// j0 = tid>>3). Loops j += 32 (64 iterations). Lanes k<4 store hoisted e[i]
// chunks (no loads in the loop); lanes k>=4 load+store e[j] chunks.
// Lane 0 writes logit, lane 1 writes te from the bitmap.
// Warp per iteration = 4 consecutive pairs * 128B = 512B contiguous stores.
// ---------------------------------------------------------------------------
__global__ void __launch_bounds__(256)
write_row(const float4* __restrict__ e4,   // [N*4] float4
          float4* __restrict__ emb_out,    // [N*N*8] float4
          float* __restrict__ logit_out,   // [N*N]
          float* __restrict__ te_out,      // [N*N]
          const float* __restrict__ bptr) {
    const unsigned i   = blockIdx.x;
    const unsigned tid = threadIdx.x;
    const unsigned k   = tid & 7u;
    const unsigned j0  = tid >> 3;         // 0..31
    const unsigned kk  = k & 3u;

    // hoisted per-thread constants
    const float4 vi  = __ldg(&e4[i * 4u + kk]);   // value for k<4 lanes
    const float  a_i = g_a[i];
    const float  bias = __ldg(bptr);
    const bool   is_i_lane = (k < 4u);

    float4* dst = emb_out + ((size_t)i * NN + j0) * 8 + k;

#pragma unroll 4
    for (unsigned j = j0; j < NN; j += 32u) {
        float4 v = is_i_lane ? vi : __ldg(&e4[j * 4u + kk]);
        *dst = v;
        if (k == 0u) {
            float lg = (i != j) ? (a_i + g_c[j] + bias) : -10.0f;
            logit_out[i * NN + j] = lg;
        } else if (k == 1u) {
            unsigned p = i * NN + j;
            unsigned bit = (g_bitmap[p >> 5] >> (p & 31u)) & 1u;
            te_out[p] = (float)bit;
        }
        dst += 32u * 8u;
    }
}

// ---------------------------------------------------------------------------
extern "C" void kernel_launch(void* const* d_in, const int* in_sizes, int n_in,
                              void* d_out, int out_size) {
    const float* emb   = (const float*)d_in[0];   // [N, 16]
    const int*   edges = (const int*)d_in[1];     // [2, E]
    const float* W     = (const float*)d_in[2];   // [1, 32]
    const float* b     = (const float*)d_in[3];   // [1]

    const int two_d = in_sizes[2];        // 32
    const int d     = two_d / 2;          // 16
    const int n     = in_sizes[0] / d;    // 2048
    const int E     = in_sizes[1] / 2;    // 65536

    float* out       = (float*)d_out;
    float* emb_out   = out;                                   // n*n*2d floats
    float* logit_out = out + (size_t)n * n * two_d;           // n*n floats
    float* te_out    = logit_out + (size_t)n * n;             // n*n floats

    // 1) per-node dots + bitmap zero (32768 threads: one uint4 each)
    precompute_and_zero<<<BITMAP_WORDS / 4 / 256, 256>>>(emb, W, n);

    // 2) scatter true-edge bits (bitmap stays in L2)
    scatter_bits<<<(E + 255) / 256, 256>>>(edges, E, n);

    // 3) fused main write: one block per row
    write_row<<<n, 256>>>((const float4*)emb, (float4*)emb_out,
                          logit_out, te_out, b);
}

// round 4
// speedup vs baseline: 1.4994x; 1.4994x over previous
#include <cuda_runtime.h>
#include <cstdint>

// Problem constants (fixed by the dataset: N=2048, DIM=16, E=65536)
#define NN 2048

// ---------------------------------------------------------------------------
// Main kernel: 8 threads per pair p = i*N + j (identical store pattern to the
// proven 94.9us R1 kernel). Thread k in [0,8):
//   k<4  -> chunk k   of e[i];  k>=4 -> chunk k-4 of e[j]
//   one STG.128 to emb_out[p*8 + k]   (warp = 4 pairs = 512B contiguous)
// Logit computed cooperatively: each lane does a 4-wide partial dot of its
// chunk with W4[k] (W offset is 4k for both halves), then shfl_xor reduce
// over the 8-lane group. Lane 0 writes logit, lane 1 writes te = 0.
// ---------------------------------------------------------------------------
__global__ void __launch_bounds__(256)
write_pairs(const float4* __restrict__ e4,   // [N*4] float4 (row = 4 float4)
            float4* __restrict__ emb_out,    // [N*N*8] float4
            float* __restrict__ logit_out,   // [N*N]
            float* __restrict__ te_out,      // [N*N]
            const float4* __restrict__ W4,   // [8] float4 (= W[32])
            const float* __restrict__ bptr) {
    size_t t = (size_t)blockIdx.x * blockDim.x + threadIdx.x;
    unsigned pair = (unsigned)(t >> 3);
    unsigned k = (unsigned)(t & 7u);
    unsigned i = pair >> 11;          // pair / 2048
    unsigned j = pair & 2047u;        // pair % 2048

    unsigned src = (k < 4u) ? (i * 4u + k) : (j * 4u + (k - 4u));
    float4 v = __ldg(&e4[src]);
    emb_out[(size_t)pair * 8 + k] = v;

    // partial dot: chunk v against W chunk k (covers both halves of W)
    float4 w = __ldg(&W4[k]);
    float s = v.x * w.x + v.y * w.y + v.z * w.z + v.w * w.w;
    s += __shfl_xor_sync(0xFFFFFFFFu, s, 4);
    s += __shfl_xor_sync(0xFFFFFFFFu, s, 2);
    s += __shfl_xor_sync(0xFFFFFFFFu, s, 1);
    // now every lane in the 8-lane group holds the full dot

    if (k == 0u) {
        logit_out[pair] = (i != j) ? (s + __ldg(bptr)) : -10.0f;
    } else if (k == 1u) {
        te_out[pair] = 0.0f;
    }
}

// ---------------------------------------------------------------------------
// Scatter (runs AFTER main): set 1.0 at true-edge positions.
// edge_list layout: [2, E] row-major -> src = el[t], dst = el[E + t]
// Duplicates all write 1.0f -> no atomics needed.
// ---------------------------------------------------------------------------
__global__ void scatter_edges(const int* __restrict__ el,
                              float* __restrict__ te, int E, int n) {
    int t = blockIdx.x * blockDim.x + threadIdx.x;
    if (t >= E) return;
    unsigned i = (unsigned)el[t];
    unsigned j = (unsigned)el[E + t];
    te[(size_t)i * n + j] = 1.0f;
}

// ---------------------------------------------------------------------------
extern "C" void kernel_launch(void* const* d_in, const int* in_sizes, int n_in,
                              void* d_out, int out_size) {
    const float* emb   = (const float*)d_in[0];   // [N, 16]
    const int*   edges = (const int*)d_in[1];     // [2, E]
    const float* W     = (const float*)d_in[2];   // [1, 32]
    const float* b     = (const float*)d_in[3];   // [1]

    const int two_d = in_sizes[2];        // 32
    const int d     = two_d / 2;          // 16
    const int n     = in_sizes[0] / d;    // 2048
    const int E     = in_sizes[1] / 2;    // 65536

    float* out       = (float*)d_out;
    float* emb_out   = out;                                   // n*n*2d floats
    float* logit_out = out + (size_t)n * n * two_d;           // n*n floats
    float* te_out    = logit_out + (size_t)n * n;             // n*n floats

    // 1) main write: 8 threads per pair, everything fused
    size_t threads = (size_t)n * n * 8;                       // 33,554,432
    unsigned blocks = (unsigned)(threads / 256);              // 131,072
    write_pairs<<<blocks, 256>>>((const float4*)emb, (float4*)emb_out,
                                 logit_out, te_out,
                                 (const float4*)W, b);

    // 2) overwrite true-edge positions with 1.0
    scatter_edges<<<(E + 255) / 256, 256>>>(edges, te_out, E, n);
}